// round 9
// baseline (speedup 1.0000x reference)
#include <cuda_runtime.h>
#include <cuda_bf16.h>

// Problem constants (fixed by the reference)
#define BATCH 16
#define MCTRL 64          // control points per axis
#define DEG   3           // degree (P == Q == 3)
#define LKNOT 68          // M + P + 1
#define OUTT  256         // OUT_U == OUT_V
#define UBLK  8           // u-rows per block

// ---------------------------------------------------------------------------
// Fused kernel: fast per-block basis recompute + separable tensor-product eval.
//
// Reference builds V from knot_u and v-linspace == u-linspace, so Nv == Nu
// and vspan == uspan: one basis table per batch serves both axes. Thread
// tid's basis IS the v-side weights for v = tid (kept in regs); the 8
// u-side weights are read from shared.
// ---------------------------------------------------------------------------
__global__ void __launch_bounds__(OUTT) surf_kernel(
    const float* __restrict__ ctrl,
    const float* __restrict__ knot_u,
    float* __restrict__ out) {
    const int b   = blockIdx.y;
    const int u0  = blockIdx.x * UBLK;
    const int tid = threadIdx.x;

    __shared__ float  U[LKNOT];
    __shared__ float4 sN[OUTT];                 // basis per t
    __shared__ int    sS[OUTT];                 // span  per t
    __shared__ float4 ts[UBLK][MCTRL + 4];      // u-contracted rows (x,y,z,pad)

    // ---- warp 0: load knots, shuffle-scan cumsum, normalize, store U ----
    if (tid < 32) {
        float vv[3];
        float carry = 0.0f;
        #pragma unroll
        for (int c = 0; c < 3; c++) {
            const int i = c * 32 + tid;
            float x = (i < LKNOT) ? knot_u[b * LKNOT + i] : 0.0f;
            #pragma unroll
            for (int d = 1; d < 32; d <<= 1) {
                float n = __shfl_up_sync(0xffffffffu, x, d);
                if (tid >= d) x += n;
            }
            x += carry;
            vv[c] = x;
            carry = __shfl_sync(0xffffffffu, x, 31);   // cs at chunk end
        }
        const float c0  = __shfl_sync(0xffffffffu, vv[0], 0);   // cs[0]
        const float inv = 1.0f / (carry - c0);
        #pragma unroll
        for (int c = 0; c < 3; c++) {
            const int i = c * 32 + tid;
            if (i < LKNOT) U[i] = (vv[c] - c0) * inv;
        }
    }
    __syncthreads();

    // ---- per-thread t: span via binary search + Cox-de Boor basis -------
    const float step = (1.0f - 2e-5f) / (float)(OUTT - 1);
    const float t    = 1e-5f + (float)tid * step;

    // Reference: first argmin over s in [3,64] of ((t-U[s])>1e-8 ? t-U[s] : 1).
    // Validity is a prefix in s (U increasing) and valid candidates strictly
    // decrease, so answer == last valid s. Binary search on the exact
    // predicate (s=3 always valid: U[3]~1e-8 << t_min-1e-8).
    int lo = DEG, hi = LKNOT - DEG;              // (3, 65]; U[65] treated invalid
    #pragma unroll
    for (int it = 0; it < 6; it++) {             // range 62 -> 6 steps
        const int mid = (lo + hi) >> 1;
        const bool valid = (t - U[mid]) > 1e-8f;
        lo = valid ? mid : lo;
        hi = valid ? hi  : mid;
    }
    const int span = lo;

    float Ni[DEG + 1];
    Ni[0] = 1.0f;
    #pragma unroll
    for (int k = 1; k <= DEG; k++) {
        float saved = 0.0f;
        #pragma unroll
        for (int r = 0; r < k; r++) {
            float K1   = U[span + r + 1];
            float K2   = U[span + 1 - k + r];
            float temp = Ni[r] / ((K1 - t) + (t - K2));
            Ni[r]      = saved + (K1 - t) * temp;
            saved      = (t - K2) * temp;
        }
        Ni[k] = saved;
    }

    sN[tid] = make_float4(Ni[0], Ni[1], Ni[2], Ni[3]);
    sS[tid] = span;
    __syncthreads();

    // ---- staging: u-contraction, 8*64 = 512 (uu, col) pairs -------------
    #pragma unroll
    for (int p = 0; p < (UBLK * MCTRL) / OUTT; p++) {
        const int idx = tid + p * OUTT;
        const int uu  = idx >> 6;           // 0..7
        const int j   = idx & 63;           // 0..63
        const float4 nu = sN[u0 + uu];
        const int    su = sS[u0 + uu] - DEG;           // 0..60
        const float4* cp = (const float4*)ctrl
                         + (size_t)b * MCTRL * MCTRL + (size_t)su * MCTRL + j;
        const float4 c0 = cp[0 * MCTRL];
        const float4 c1 = cp[1 * MCTRL];
        const float4 c2 = cp[2 * MCTRL];
        const float4 c3 = cp[3 * MCTRL];
        float x = nu.x * c0.x, y = nu.x * c0.y, z = nu.x * c0.z;
        x = fmaf(nu.y, c1.x, x); y = fmaf(nu.y, c1.y, y); z = fmaf(nu.y, c1.z, z);
        x = fmaf(nu.z, c2.x, x); y = fmaf(nu.z, c2.y, y); z = fmaf(nu.z, c2.z, z);
        x = fmaf(nu.w, c3.x, x); y = fmaf(nu.w, c3.y, y); z = fmaf(nu.w, c3.z, z);
        ts[uu][j] = make_float4(x, y, z, 0.0f);        // one STS.128
    }
    if (tid < UBLK * 4) {                   // pad (sv <= 60 analytically)
        const int uu = tid >> 2, j = tid & 3;
        ts[uu][MCTRL + j] = make_float4(0.0f, 0.0f, 0.0f, 0.0f);
    }
    __syncthreads();

    // ---- v-contraction: weights already in registers, 4 LDS.128/point ---
    const int sv = span - DEG;              // 0..60
    float* obase = out + ((size_t)(b * OUTT + u0) * OUTT + tid) * 3;
    #pragma unroll
    for (int uu = 0; uu < UBLK; uu++) {
        const float4 a = ts[uu][sv];
        const float4 c = ts[uu][sv + 1];
        const float4 d = ts[uu][sv + 2];
        const float4 e = ts[uu][sv + 3];
        float ax = Ni[0] * a.x, ay = Ni[0] * a.y, az = Ni[0] * a.z;
        ax = fmaf(Ni[1], c.x, ax); ay = fmaf(Ni[1], c.y, ay); az = fmaf(Ni[1], c.z, az);
        ax = fmaf(Ni[2], d.x, ax); ay = fmaf(Ni[2], d.y, ay); az = fmaf(Ni[2], d.z, az);
        ax = fmaf(Ni[3], e.x, ax); ay = fmaf(Ni[3], e.y, ay); az = fmaf(Ni[3], e.z, az);
        float* o = obase + (size_t)uu * OUTT * 3;
        o[0] = ax; o[1] = ay; o[2] = az;
    }
}

// ---------------------------------------------------------------------------
extern "C" void kernel_launch(void* const* d_in, const int* in_sizes, int n_in,
                              void* d_out, int out_size) {
    const float* ctrl   = (const float*)d_in[0];   // [16,64,64,4]
    const float* knot_u = (const float*)d_in[1];   // [16,68]
    (void)in_sizes; (void)n_in; (void)out_size;

    float* out = (float*)d_out;                    // [16,256,256,3]

    dim3 grid(OUTT / UBLK, BATCH);
    surf_kernel<<<grid, OUTT>>>(ctrl, knot_u, out);
}

// round 13
// speedup vs baseline: 1.5134x; 1.5134x over previous
#include <cuda_runtime.h>
#include <cuda_bf16.h>

// Problem constants (fixed by the reference)
#define BATCH 16
#define MCTRL 64          // control points per axis
#define DEG   3           // degree (P == Q == 3)
#define LKNOT 68          // M + P + 1
#define OUTT  256         // OUT_U == OUT_V
#define UBLK  8           // u-rows per block
#define SPAN_LO DEG              // 3
#define SPAN_HI (LKNOT - DEG - 1) // 64

// ---------------------------------------------------------------------------
// Fused kernel. Reference builds V from knot_u and v-linspace == u-linspace,
// so Nv == Nu, vspan == uspan: one basis/span table serves both axes.
//
// Span via scatter: boundaries iLo[s] (first t-index where knot s becomes
// valid) are computed by 63 threads with the exact reference predicate, then
// scattered into a per-t span table. Each thread then reads its span with a
// single LDS instead of a 62-way scan.
// ---------------------------------------------------------------------------
__global__ void __launch_bounds__(OUTT) surf_kernel(
    const float* __restrict__ ctrl,
    const float* __restrict__ knot_u,
    float* __restrict__ out) {
    const int b   = blockIdx.y;
    const int u0  = blockIdx.x * UBLK;
    const int tid = threadIdx.x;

    __shared__ float  U[LKNOT];
    __shared__ int    iLo[LKNOT];               // boundaries, idx 3..65 used
    __shared__ float4 sN[OUTT];                 // basis per t
    __shared__ int    sS[OUTT];                 // span  per t
    __shared__ float  ts[UBLK][3][MCTRL + 4];   // u-contracted rows (x,y,z)

    const float step = (1.0f - 2e-5f) / (float)(OUTT - 1);

    // ---- warp 0: load knots, shuffle-scan cumsum, normalize, store U ----
    if (tid < 32) {
        float vv[3];
        float carry = 0.0f;
        #pragma unroll
        for (int c = 0; c < 3; c++) {
            const int i = c * 32 + tid;
            float x = (i < LKNOT) ? knot_u[b * LKNOT + i] : 0.0f;
            #pragma unroll
            for (int d = 1; d < 32; d <<= 1) {
                float n = __shfl_up_sync(0xffffffffu, x, d);
                if (tid >= d) x += n;
            }
            x += carry;
            vv[c] = x;
            carry = __shfl_sync(0xffffffffu, x, 31);   // cs at chunk end
        }
        const float c0  = __shfl_sync(0xffffffffu, vv[0], 0);   // cs[0]
        const float inv = 1.0f / (carry - c0);
        #pragma unroll
        for (int c = 0; c < 3; c++) {
            const int i = c * 32 + tid;
            if (i < LKNOT) U[i] = (vv[c] - c0) * inv;
        }
    }
    __syncthreads();

    // ---- span boundaries: thread tid handles s = tid + 3 (s = 3..65) ----
    if (tid <= SPAN_HI - SPAN_LO + 1) {          // tid 0..62 -> s 3..65
        const int s = tid + SPAN_LO;
        int lo;
        if (s > SPAN_HI) {
            lo = OUTT;                            // sentinel for s = 65
        } else {
            const float Us = U[s];
            // estimate first i with (t_i - Us) > 1e-8 ; start 2 early, fix
            // forward with the EXACT reference predicate (pure arithmetic).
            float est = (Us + 1e-8f - 1e-5f) / step;
            int i = (int)est - 2;
            i = (i < 0) ? 0 : ((i > OUTT) ? OUTT : i);
            #pragma unroll 1
            while (i < OUTT) {
                const float t_i = 1e-5f + (float)i * step;
                if ((t_i - Us) > 1e-8f) break;
                i++;
            }
            lo = i;
        }
        iLo[s] = lo;
    }
    __syncthreads();

    // ---- scatter span values: span(i) = last valid s ("last valid" ==
    // reference first-argmin over strictly-decreasing valid candidates) ----
    if (tid <= SPAN_HI - SPAN_LO) {              // tid 0..61 -> s 3..64
        const int s  = tid + SPAN_LO;
        const int lo = iLo[s];
        const int hi = iLo[s + 1];
        #pragma unroll 1
        for (int i = lo; i < hi; i++) sS[i] = s;
    }
    __syncthreads();

    // ---- per-thread t: span lookup + Cox-de Boor basis (fast div) -------
    const float t    = 1e-5f + (float)tid * step;
    const int   span = sS[tid];

    float Ni[DEG + 1];
    Ni[0] = 1.0f;
    #pragma unroll
    for (int k = 1; k <= DEG; k++) {
        float saved = 0.0f;
        #pragma unroll
        for (int r = 0; r < k; r++) {
            float K1   = U[span + r + 1];
            float K2   = U[span + 1 - k + r];
            float temp = __fdividef(Ni[r], (K1 - t) + (t - K2));
            Ni[r]      = saved + (K1 - t) * temp;
            saved      = (t - K2) * temp;
        }
        Ni[k] = saved;
    }

    sN[tid] = make_float4(Ni[0], Ni[1], Ni[2], Ni[3]);
    __syncthreads();

    // ---- staging: u-contraction, 8*64 = 512 (uu, col) pairs -------------
    #pragma unroll
    for (int p = 0; p < (UBLK * MCTRL) / OUTT; p++) {
        const int idx = tid + p * OUTT;
        const int uu  = idx >> 6;           // 0..7
        const int j   = idx & 63;           // 0..63
        const float4 nu = sN[u0 + uu];
        const int    su = sS[u0 + uu] - DEG;           // 0..60
        const float4* cp = (const float4*)ctrl
                         + (size_t)b * MCTRL * MCTRL + (size_t)su * MCTRL + j;
        const float4 c0 = cp[0 * MCTRL];
        const float4 c1 = cp[1 * MCTRL];
        const float4 c2 = cp[2 * MCTRL];
        const float4 c3 = cp[3 * MCTRL];
        float x = nu.x * c0.x, y = nu.x * c0.y, z = nu.x * c0.z;
        x = fmaf(nu.y, c1.x, x); y = fmaf(nu.y, c1.y, y); z = fmaf(nu.y, c1.z, z);
        x = fmaf(nu.z, c2.x, x); y = fmaf(nu.z, c2.y, y); z = fmaf(nu.z, c2.z, z);
        x = fmaf(nu.w, c3.x, x); y = fmaf(nu.w, c3.y, y); z = fmaf(nu.w, c3.z, z);
        ts[uu][0][j] = x; ts[uu][1][j] = y; ts[uu][2][j] = z;
    }
    if (tid < UBLK * 4) {                   // pad (sv <= 60 analytically)
        const int uu = tid >> 2, j = tid & 3;
        ts[uu][0][MCTRL + j] = 0.0f;
        ts[uu][1][MCTRL + j] = 0.0f;
        ts[uu][2][MCTRL + j] = 0.0f;
    }
    __syncthreads();

    // ---- v-contraction: weights already in registers -------------------
    const int sv = span - DEG;              // 0..60
    float* obase = out + ((size_t)(b * OUTT + u0) * OUTT + tid) * 3;
    #pragma unroll
    for (int uu = 0; uu < UBLK; uu++) {
        const float* px = ts[uu][0];
        const float* py = ts[uu][1];
        const float* pz = ts[uu][2];
        float ax = Ni[0] * px[sv];
        float ay = Ni[0] * py[sv];
        float az = Ni[0] * pz[sv];
        ax = fmaf(Ni[1], px[sv + 1], ax); ay = fmaf(Ni[1], py[sv + 1], ay); az = fmaf(Ni[1], pz[sv + 1], az);
        ax = fmaf(Ni[2], px[sv + 2], ax); ay = fmaf(Ni[2], py[sv + 2], ay); az = fmaf(Ni[2], pz[sv + 2], az);
        ax = fmaf(Ni[3], px[sv + 3], ax); ay = fmaf(Ni[3], py[sv + 3], ay); az = fmaf(Ni[3], pz[sv + 3], az);
        float* o = obase + (size_t)uu * OUTT * 3;
        o[0] = ax; o[1] = ay; o[2] = az;
    }
}

// ---------------------------------------------------------------------------
extern "C" void kernel_launch(void* const* d_in, const int* in_sizes, int n_in,
                              void* d_out, int out_size) {
    const float* ctrl   = (const float*)d_in[0];   // [16,64,64,4]
    const float* knot_u = (const float*)d_in[1];   // [16,68]
    (void)in_sizes; (void)n_in; (void)out_size;

    float* out = (float*)d_out;                    // [16,256,256,3]

    dim3 grid(OUTT / UBLK, BATCH);
    surf_kernel<<<grid, OUTT>>>(ctrl, knot_u, out);
}